// round 1
// baseline (speedup 1.0000x reference)
#include <cuda_runtime.h>
#include <cstdint>
#include <cstddef>

// Problem constants (fixed by the dataset)
#define NN 100000
#define EE 1600000
#define IN_CH 41
#define ED 8
#define HH 64
#define LL 3
#define GG 256
#define ATOM 21
#define EPSN 1e-5f

// ---------------- scratch buffers (device globals; no allocation) ----------
static __device__ float4 g_hbuf[(size_t)NN * HH / 4];     // h
static __device__ float4 g_h2buf[(size_t)NN * HH / 4];    // h2 (pre-norm)
static __device__ float4 g_tbuf[(size_t)NN * HH / 4];     // mlp hidden
static __device__ float4 g_aggrbuf[(size_t)NN * HH / 4];  // edge aggregation
static __device__ float g_gmean[GG * HH];
static __device__ float g_grstd[GG * HH];
static __device__ int g_maskbuf[NN];

// ---------------- helpers ---------------------------------------------------
__device__ __forceinline__ int lower_bound_dev(const int* __restrict__ arr, int n, int val) {
    int lo = 0, hi = n;
    while (lo < hi) {
        int mid = (lo + hi) >> 1;
        if (__ldg(&arr[mid]) < val) lo = mid + 1; else hi = mid;
    }
    return lo;
}

// ---------------- encoder pass 1: t = relu(x @ W1_sel + b1_sel) ------------
__global__ void __launch_bounds__(128) k_enc1(
    const float* __restrict__ x,
    const float* __restrict__ Wl, const float* __restrict__ bl,
    const float* __restrict__ Wp, const float* __restrict__ bp,
    float* __restrict__ out, int* __restrict__ mask)
{
    __shared__ __align__(16) float sWl[IN_CH * HH];
    __shared__ __align__(16) float sWp[IN_CH * HH];
    __shared__ float sBl[HH], sBp[HH];
    for (int i = threadIdx.x; i < IN_CH * HH; i += 128) { sWl[i] = Wl[i]; sWp[i] = Wp[i]; }
    if (threadIdx.x < HH) { sBl[threadIdx.x] = bl[threadIdx.x]; sBp[threadIdx.x] = bp[threadIdx.x]; }
    __syncthreads();

    int node = blockIdx.x * 128 + threadIdx.x;
    if (node >= NN) return;
    const float* xp = x + (size_t)node * IN_CH;

    float s = 0.0f;
#pragma unroll
    for (int k = ATOM; k < IN_CH; k++) s += fabsf(__ldg(&xp[k]));
    bool prot = s > 1e-6f;
    mask[node] = prot ? 1 : 0;

    const float* sW = prot ? sWp : sWl;
    const float* sB = prot ? sBp : sBl;

    float acc[HH];
#pragma unroll
    for (int j = 0; j < HH; j++) acc[j] = sB[j];

    for (int k = 0; k < IN_CH; k++) {
        float xk = __ldg(&xp[k]);
#pragma unroll
        for (int j = 0; j < HH; j += 4) {
            float4 w = *reinterpret_cast<const float4*>(&sW[k * HH + j]);
            acc[j + 0] = fmaf(xk, w.x, acc[j + 0]);
            acc[j + 1] = fmaf(xk, w.y, acc[j + 1]);
            acc[j + 2] = fmaf(xk, w.z, acc[j + 2]);
            acc[j + 3] = fmaf(xk, w.w, acc[j + 3]);
        }
    }
    float4* op = reinterpret_cast<float4*>(out + (size_t)node * HH);
#pragma unroll
    for (int j = 0; j < HH; j += 4) {
        float4 v;
        v.x = fmaxf(acc[j + 0], 0.f);
        v.y = fmaxf(acc[j + 1], 0.f);
        v.z = fmaxf(acc[j + 2], 0.f);
        v.w = fmaxf(acc[j + 3], 0.f);
        op[j >> 2] = v;
    }
}

// ---------------- encoder pass 2: h = relu(t @ W2_sel + b2_sel) -------------
__global__ void __launch_bounds__(128) k_dense_dual(
    const float* __restrict__ in,
    const float* __restrict__ Wl, const float* __restrict__ bl,
    const float* __restrict__ Wp, const float* __restrict__ bp,
    const int* __restrict__ mask,
    float* __restrict__ out)
{
    __shared__ __align__(16) float sWl[HH * HH];
    __shared__ __align__(16) float sWp[HH * HH];
    __shared__ float sBl[HH], sBp[HH];
    for (int i = threadIdx.x; i < HH * HH; i += 128) { sWl[i] = Wl[i]; sWp[i] = Wp[i]; }
    if (threadIdx.x < HH) { sBl[threadIdx.x] = bl[threadIdx.x]; sBp[threadIdx.x] = bp[threadIdx.x]; }
    __syncthreads();

    int node = blockIdx.x * 128 + threadIdx.x;
    if (node >= NN) return;
    bool prot = mask[node] != 0;
    const float* sW = prot ? sWp : sWl;
    const float* sB = prot ? sBp : sBl;
    const float* ip = in + (size_t)node * HH;

    float acc[HH];
#pragma unroll
    for (int j = 0; j < HH; j++) acc[j] = sB[j];

    for (int k = 0; k < HH; k++) {
        float zk = __ldg(&ip[k]);
#pragma unroll
        for (int j = 0; j < HH; j += 4) {
            float4 w = *reinterpret_cast<const float4*>(&sW[k * HH + j]);
            acc[j + 0] = fmaf(zk, w.x, acc[j + 0]);
            acc[j + 1] = fmaf(zk, w.y, acc[j + 1]);
            acc[j + 2] = fmaf(zk, w.z, acc[j + 2]);
            acc[j + 3] = fmaf(zk, w.w, acc[j + 3]);
        }
    }
    float4* op = reinterpret_cast<float4*>(out + (size_t)node * HH);
#pragma unroll
    for (int j = 0; j < HH; j += 4) {
        float4 v;
        v.x = fmaxf(acc[j + 0], 0.f);
        v.y = fmaxf(acc[j + 1], 0.f);
        v.z = fmaxf(acc[j + 2], 0.f);
        v.w = fmaxf(acc[j + 3], 0.f);
        op[j >> 2] = v;
    }
}

// ---------------- generic 64x64 dense: out = [relu](in (+add)) @ W + b ------
template <bool HAS_ADD, bool RELU>
__global__ void __launch_bounds__(128) k_dense64(
    const float* __restrict__ in, const float* __restrict__ add,
    const float* __restrict__ W, const float* __restrict__ bias,
    float* __restrict__ out)
{
    __shared__ __align__(16) float sW[HH * HH];
    __shared__ float sB[HH];
    for (int i = threadIdx.x; i < HH * HH; i += 128) sW[i] = W[i];
    if (threadIdx.x < HH) sB[threadIdx.x] = bias[threadIdx.x];
    __syncthreads();

    int node = blockIdx.x * 128 + threadIdx.x;
    if (node >= NN) return;
    const float* ip = in + (size_t)node * HH;
    const float* ap = HAS_ADD ? (add + (size_t)node * HH) : nullptr;

    float acc[HH];
#pragma unroll
    for (int j = 0; j < HH; j++) acc[j] = sB[j];

    for (int k = 0; k < HH; k++) {
        float zk = __ldg(&ip[k]);
        if (HAS_ADD) zk += __ldg(&ap[k]);
#pragma unroll
        for (int j = 0; j < HH; j += 4) {
            float4 w = *reinterpret_cast<const float4*>(&sW[k * HH + j]);
            acc[j + 0] = fmaf(zk, w.x, acc[j + 0]);
            acc[j + 1] = fmaf(zk, w.y, acc[j + 1]);
            acc[j + 2] = fmaf(zk, w.z, acc[j + 2]);
            acc[j + 3] = fmaf(zk, w.w, acc[j + 3]);
        }
    }
    float4* op = reinterpret_cast<float4*>(out + (size_t)node * HH);
#pragma unroll
    for (int j = 0; j < HH; j += 4) {
        float4 v = make_float4(acc[j], acc[j + 1], acc[j + 2], acc[j + 3]);
        if (RELU) {
            v.x = fmaxf(v.x, 0.f); v.y = fmaxf(v.y, 0.f);
            v.z = fmaxf(v.z, 0.f); v.w = fmaxf(v.w, 0.f);
        }
        op[j >> 2] = v;
    }
}

// ---------------- edge kernel: aggr[dst] += relu(h[src] + ea@We + be) -------
// 16 threads per edge, 4 features each, vector RED to L2.
__global__ void __launch_bounds__(256) k_edge(
    const float* __restrict__ h,
    const int* __restrict__ src, const int* __restrict__ dst,
    const float* __restrict__ ea,
    const float* __restrict__ We, const float* __restrict__ be,
    float* __restrict__ aggr)
{
    __shared__ __align__(16) float sW[ED * HH];  // 512
    __shared__ float sB[HH];
    __shared__ float sEA[16 * ED];               // 128
    __shared__ int sSrc[16], sDst[16];

    int tid = threadIdx.x;
    for (int i = tid; i < ED * HH; i += 256) sW[i] = We[i];
    if (tid < HH) sB[tid] = be[tid];

    int e0 = blockIdx.x * 16;
    if (tid < 16 * ED) {
        int e = e0 + (tid >> 3);
        sEA[tid] = (e < EE) ? ea[(size_t)e * ED + (tid & 7)] : 0.0f;
    }
    if (tid < 16) {
        int e = e0 + tid;
        sSrc[tid] = (e < EE) ? __ldg(&src[e]) : 0;
        sDst[tid] = (e < EE) ? __ldg(&dst[e]) : -1;
    }
    __syncthreads();

    int le = tid >> 4;
    int lf = (tid & 15) * 4;
    int e = e0 + le;
    if (e >= EE) return;
    int s = sSrc[le];
    int d = sDst[le];

    float4 hv = *reinterpret_cast<const float4*>(h + (size_t)s * HH + lf);
    float4 acc = make_float4(sB[lf], sB[lf + 1], sB[lf + 2], sB[lf + 3]);
#pragma unroll
    for (int k = 0; k < ED; k++) {
        float a = sEA[le * ED + k];
        float4 w = *reinterpret_cast<const float4*>(&sW[k * HH + lf]);
        acc.x = fmaf(a, w.x, acc.x);
        acc.y = fmaf(a, w.y, acc.y);
        acc.z = fmaf(a, w.z, acc.z);
        acc.w = fmaf(a, w.w, acc.w);
    }
    float m0 = fmaxf(hv.x + acc.x, 0.f);
    float m1 = fmaxf(hv.y + acc.y, 0.f);
    float m2 = fmaxf(hv.z + acc.z, 0.f);
    float m3 = fmaxf(hv.w + acc.w, 0.f);

    float* p = aggr + (size_t)d * HH + lf;
    asm volatile("red.global.add.v4.f32 [%0], {%1,%2,%3,%4};"
                 :: "l"(p), "f"(m0), "f"(m1), "f"(m2), "f"(m3) : "memory");
}

// ---------------- GraphNorm stats: block per graph (batch is sorted) --------
// One pass: S = sum h, Q = sum h^2; var(o) = Q/c - m^2 * a * (2 - a), o = h - a*m
__global__ void __launch_bounds__(256) k_stats(
    const float* __restrict__ h2, const int* __restrict__ batch,
    const float* __restrict__ alpha,
    float* __restrict__ gmean, float* __restrict__ grstd)
{
    int g = blockIdx.x;
    int start = lower_bound_dev(batch, NN, g);
    int end = lower_bound_dev(batch, NN, g + 1);

    int tid = threadIdx.x;
    int f = tid & 63;
    int slot = tid >> 6;  // 0..3
    float s = 0.f, q = 0.f;
    for (int i = start + slot; i < end; i += 4) {
        float v = __ldg(&h2[(size_t)i * HH + f]);
        s += v;
        q = fmaf(v, v, q);
    }
    __shared__ float ss[256], sq[256];
    ss[tid] = s; sq[tid] = q;
    __syncthreads();
    if (tid < HH) {
        float S = ss[tid] + ss[tid + 64] + ss[tid + 128] + ss[tid + 192];
        float Q = sq[tid] + sq[tid + 64] + sq[tid + 128] + sq[tid + 192];
        float cnt = fmaxf((float)(end - start), 1.0f);
        float m = S / cnt;
        float m2 = Q / cnt;
        float a = __ldg(&alpha[tid]);
        float var = m2 - m * m * a * (2.0f - a);
        gmean[g * HH + tid] = m;
        grstd[g * HH + tid] = rsqrtf(var + EPSN);
    }
}

// ---------------- GraphNorm apply + relu ------------------------------------
__global__ void __launch_bounds__(256) k_finalize(
    const float* __restrict__ h2, const int* __restrict__ batch,
    const float* __restrict__ gmean, const float* __restrict__ grstd,
    const float* __restrict__ w, const float* __restrict__ b,
    const float* __restrict__ alpha,
    float* __restrict__ hout)
{
    size_t idx = (size_t)blockIdx.x * blockDim.x + threadIdx.x;
    if (idx >= (size_t)NN * HH) return;
    int i = (int)(idx >> 6);
    int f = (int)(idx & 63);
    int g = __ldg(&batch[i]);
    float m = __ldg(&gmean[g * HH + f]);
    float r = __ldg(&grstd[g * HH + f]);
    float o = __ldg(&h2[idx]) - __ldg(&alpha[f]) * m;
    hout[idx] = fmaxf(fmaf(__ldg(&w[f]), o * r, __ldg(&b[f])), 0.f);
}

// ---------------- pool + readout: block per graph ---------------------------
__global__ void __launch_bounds__(128) k_readout(
    const float* __restrict__ h, const int* __restrict__ batch,
    const float* __restrict__ W1, const float* __restrict__ b1,
    const float* __restrict__ W2, const float* __restrict__ b2,
    float* __restrict__ out)
{
    int g = blockIdx.x;
    int start = lower_bound_dev(batch, NN, g);
    int end = lower_bound_dev(batch, NN, g + 1);

    int tid = threadIdx.x;
    int f = tid & 63;
    int slot = tid >> 6;  // 0..1
    float s = 0.f;
    for (int i = start + slot; i < end; i += 2)
        s += __ldg(&h[(size_t)i * HH + f]);

    __shared__ float sp[128];
    __shared__ float pool[HH];
    __shared__ float tv[HH];
    sp[tid] = s;
    __syncthreads();
    if (tid < HH) pool[tid] = sp[tid] + sp[tid + 64];
    __syncthreads();
    if (tid < HH) {
        float acc = __ldg(&b1[tid]);
#pragma unroll
        for (int k = 0; k < HH; k++)
            acc = fmaf(pool[k], __ldg(&W1[k * HH + tid]), acc);
        tv[tid] = fmaxf(acc, 0.f) * __ldg(&W2[tid]);
    }
    __syncthreads();
    if (tid == 0) {
        float r = __ldg(b2);
#pragma unroll
        for (int k = 0; k < HH; k++) r += tv[k];
        out[g] = r;
    }
}

// ---------------- launch ----------------------------------------------------
extern "C" void kernel_launch(void* const* d_in, const int* in_sizes, int n_in,
                              void* d_out, int out_size)
{
    const float* x       = (const float*)d_in[0];
    const int*   ei      = (const int*)d_in[1];
    const float* ea      = (const float*)d_in[2];
    const int*   batch   = (const int*)d_in[3];
    const float* lig_W1  = (const float*)d_in[4];
    const float* lig_b1  = (const float*)d_in[5];
    const float* lig_W2  = (const float*)d_in[6];
    const float* lig_b2  = (const float*)d_in[7];
    const float* prot_W1 = (const float*)d_in[8];
    const float* prot_b1 = (const float*)d_in[9];
    const float* prot_W2 = (const float*)d_in[10];
    const float* prot_b2 = (const float*)d_in[11];
    const float* conv_We = (const float*)d_in[12];
    const float* conv_be = (const float*)d_in[13];
    const float* conv_W1 = (const float*)d_in[14];
    const float* conv_b1 = (const float*)d_in[15];
    const float* conv_W2 = (const float*)d_in[16];
    const float* conv_b2 = (const float*)d_in[17];
    const float* norm_w  = (const float*)d_in[18];
    const float* norm_b  = (const float*)d_in[19];
    const float* norm_a  = (const float*)d_in[20];
    const float* out_W1  = (const float*)d_in[21];
    const float* out_b1  = (const float*)d_in[22];
    const float* out_W2  = (const float*)d_in[23];
    const float* out_b2  = (const float*)d_in[24];
    float* out = (float*)d_out;

    const int* src = ei;
    const int* dst = ei + EE;

    void *ph, *ph2, *pt, *pag, *pgm, *pgr, *pmask;
    cudaGetSymbolAddress(&ph,   g_hbuf);
    cudaGetSymbolAddress(&ph2,  g_h2buf);
    cudaGetSymbolAddress(&pt,   g_tbuf);
    cudaGetSymbolAddress(&pag,  g_aggrbuf);
    cudaGetSymbolAddress(&pgm,  g_gmean);
    cudaGetSymbolAddress(&pgr,  g_grstd);
    cudaGetSymbolAddress(&pmask, g_maskbuf);
    float* h    = (float*)ph;
    float* h2   = (float*)ph2;
    float* t    = (float*)pt;
    float* aggr = (float*)pag;
    float* gmean = (float*)pgm;
    float* grstd = (float*)pgr;
    int*   mask  = (int*)pmask;

    const int nodeBlocks = (NN + 127) / 128;

    // encoder
    k_enc1<<<nodeBlocks, 128>>>(x, lig_W1, lig_b1, prot_W1, prot_b1, t, mask);
    k_dense_dual<<<nodeBlocks, 128>>>(t, lig_W2, lig_b2, prot_W2, prot_b2, mask, h);

    for (int l = 0; l < LL; l++) {
        cudaMemsetAsync(aggr, 0, (size_t)NN * HH * sizeof(float));
        k_edge<<<(EE + 15) / 16, 256>>>(h, src, dst, ea,
                                        conv_We + l * ED * HH, conv_be + l * HH, aggr);
        // t = relu((h + aggr) @ W1 + b1)
        k_dense64<true, true><<<nodeBlocks, 128>>>(h, aggr, conv_W1 + l * HH * HH,
                                                   conv_b1 + l * HH, t);
        // h2 = t @ W2 + b2
        k_dense64<false, false><<<nodeBlocks, 128>>>(t, nullptr, conv_W2 + l * HH * HH,
                                                     conv_b2 + l * HH, h2);
        // GraphNorm
        k_stats<<<GG, 256>>>(h2, batch, norm_a + l * HH, gmean, grstd);
        k_finalize<<<((size_t)NN * HH + 255) / 256, 256>>>(
            h2, batch, gmean, grstd, norm_w + l * HH, norm_b + l * HH, norm_a + l * HH, h);
    }

    k_readout<<<GG, 128>>>(h, batch, out_W1, out_b1, out_W2, out_b2, out);
}